// round 15
// baseline (speedup 1.0000x reference)
#include <cuda_runtime.h>

// GraphAttentionPooling: B=32, N=3072, F=256, P=3 -> 32768 windows (16384 pairs).
// Persistent 444 blocks (3/SM) x 256 thr. Each warp grid-strides over PAIRS of
// consecutive windows, SINGLE-buffered: 12 independent LDG.128 issued up front,
// L2 latency (~250cyc, covered by prefetch.global.L2 PD pairs ahead) paid once
// per 2 windows. ~80 regs -> 24 warps/SM.

#define F_DIM 256
#define P_DIM 3
#define NUM_SMS 148
#define BLOCKS_PER_SM 3
#define THREADS_PER_BLOCK 256
#define PD 3   // prefetch distance in PAIRS (6KB each)

__device__ __forceinline__ float warp_reduce_sum(float v) {
    #pragma unroll
    for (int off = 16; off > 0; off >>= 1)
        v += __shfl_xor_sync(0xFFFFFFFFu, v, off);
    return v;
}

__device__ __forceinline__ float dot8(float4 a, float4 b, float4 wa, float4 wb) {
    float s = a.x * wa.x;
    s = fmaf(a.y, wa.y, s);
    s = fmaf(a.z, wa.z, s);
    s = fmaf(a.w, wa.w, s);
    s = fmaf(b.x, wb.x, s);
    s = fmaf(b.y, wb.y, s);
    s = fmaf(b.z, wb.z, s);
    s = fmaf(b.w, wb.w, s);
    return s;
}

// Softmax over 3 + weighted combine + streaming store for one window.
__device__ __forceinline__ void finish_window(
    float s0, float s1, float s2,
    float4 r0a, float4 r0b, float4 r1a, float4 r1b, float4 r2a, float4 r2b,
    float4* o)
{
    float m = fmaxf(s0, fmaxf(s1, s2));
    float e0 = __expf(s0 - m);
    float e1 = __expf(s1 - m);
    float e2 = __expf(s2 - m);
    float inv = 1.0f / (e0 + e1 + e2);
    float a0 = e0 * inv, a1 = e1 * inv, a2 = e2 * inv;

    float4 oa, ob;
    oa.x = fmaf(r2a.x, a2, fmaf(r1a.x, a1, r0a.x * a0));
    oa.y = fmaf(r2a.y, a2, fmaf(r1a.y, a1, r0a.y * a0));
    oa.z = fmaf(r2a.z, a2, fmaf(r1a.z, a1, r0a.z * a0));
    oa.w = fmaf(r2a.w, a2, fmaf(r1a.w, a1, r0a.w * a0));
    ob.x = fmaf(r2b.x, a2, fmaf(r1b.x, a1, r0b.x * a0));
    ob.y = fmaf(r2b.y, a2, fmaf(r1b.y, a1, r0b.y * a0));
    ob.z = fmaf(r2b.z, a2, fmaf(r1b.z, a1, r0b.z * a0));
    ob.w = fmaf(r2b.w, a2, fmaf(r1b.w, a1, r0b.w * a0));

    __stcs(o,     oa);
    __stcs(o + 1, ob);
}

__global__ void __launch_bounds__(THREADS_PER_BLOCK, BLOCKS_PER_SM)
gap_kernel(const float* __restrict__ x,
           const float* __restrict__ Ww,
           const float* __restrict__ Wb,
           float* __restrict__ out,
           int n_pairs) {
    const int warp_id = (blockIdx.x * blockDim.x + threadIdx.x) >> 5;
    const int lane    = threadIdx.x & 31;
    const int n_warps = (int)((gridDim.x * blockDim.x) >> 5);

    if (warp_id >= n_pairs) return;

    const int fv = lane * 2;  // float4 index within a row (row = 64 float4)

    const float4* Wv = reinterpret_cast<const float4*>(Ww);
    const float4 wa = Wv[fv], wb = Wv[fv + 1];
    const float bias = Wb[0];

    const float4* xbase = reinterpret_cast<const float4*>(x);
    float4*       obase = reinterpret_cast<float4*>(out);

    // Prologue: L2-prefetch the first PD pairs of this warp's stream.
    // Pair = 6144 B = 48 lines; lanes 0..23 take 2 lines each (both windows).
    if (lane < 24) {
        #pragma unroll
        for (int d = 0; d < PD; d++) {
            long long pi = warp_id + (long long)d * n_warps;
            if (pi < n_pairs) {
                const char* p = (const char*)x + pi * 6144 + lane * 128;
                asm volatile("prefetch.global.L2 [%0];" :: "l"(p));
                asm volatile("prefetch.global.L2 [%0];" :: "l"(p + 3072));
            }
        }
    }

    for (int p = warp_id; p < n_pairs; p += n_warps) {
        // L2-prefetch the pair PD iterations ahead (registerless).
        {
            long long pp = p + (long long)PD * n_warps;
            if (pp < n_pairs && lane < 24) {
                const char* q = (const char*)x + pp * 6144 + lane * 128;
                asm volatile("prefetch.global.L2 [%0];" :: "l"(q));
                asm volatile("prefetch.global.L2 [%0];" :: "l"(q + 3072));
            }
        }

        // 12 independent LDG.128 for both windows of the pair (384 float4 span).
        const float4* xp = xbase + (long long)p * 384 + fv;
        float4 A0a = __ldcs(xp +   0), A0b = __ldcs(xp +   1);
        float4 A1a = __ldcs(xp +  64), A1b = __ldcs(xp +  65);
        float4 A2a = __ldcs(xp + 128), A2b = __ldcs(xp + 129);
        float4 B0a = __ldcs(xp + 192), B0b = __ldcs(xp + 193);
        float4 B1a = __ldcs(xp + 256), B1b = __ldcs(xp + 257);
        float4 B2a = __ldcs(xp + 320), B2b = __ldcs(xp + 321);

        // Six independent reduction chains (good SHFL latency overlap).
        float sA0 = warp_reduce_sum(dot8(A0a, A0b, wa, wb)) + bias;
        float sA1 = warp_reduce_sum(dot8(A1a, A1b, wa, wb)) + bias;
        float sA2 = warp_reduce_sum(dot8(A2a, A2b, wa, wb)) + bias;
        float sB0 = warp_reduce_sum(dot8(B0a, B0b, wa, wb)) + bias;
        float sB1 = warp_reduce_sum(dot8(B1a, B1b, wa, wb)) + bias;
        float sB2 = warp_reduce_sum(dot8(B2a, B2b, wa, wb)) + bias;

        float4* o = obase + (long long)p * 128 + fv;  // 2 windows * 64 float4
        finish_window(sA0, sA1, sA2, A0a, A0b, A1a, A1b, A2a, A2b, o);
        finish_window(sB0, sB1, sB2, B0a, B0b, B1a, B1b, B2a, B2b, o + 64);
    }
}

extern "C" void kernel_launch(void* const* d_in, const int* in_sizes, int n_in,
                              void* d_out, int out_size) {
    const float* x  = (const float*)d_in[0];  // [32, 3072, 256]
    const float* Ww = (const float*)d_in[1];  // [256]
    const float* Wb = (const float*)d_in[2];  // [1]
    float* out = (float*)d_out;               // [32, 1024, 256, 1]

    const int n_windows = in_sizes[0] / (P_DIM * F_DIM);  // 32768
    const int n_pairs   = n_windows / 2;                  // 16384
    const int blocks    = NUM_SMS * BLOCKS_PER_SM;        // 444, exact-fit one wave

    gap_kernel<<<blocks, THREADS_PER_BLOCK>>>(x, Ww, Wb, out, n_pairs);
}

// round 16
// speedup vs baseline: 1.1082x; 1.1082x over previous
#include <cuda_runtime.h>

// GraphAttentionPooling: B=32, N=3072, F=256, P=3 -> S=1024, 32768 windows.
// Champion core (R14, 20.96us): grid-stride, depth-1 register double-buffer,
// explicit prefetch.global.L2 PD ahead, peeled final iteration.
// R16: same 3552 warps repartitioned as 888 blocks x 128 thr (6 blocks/SM,
// 4 warps each) -- identical per-warp streams, finer CTA granularity for a
// smoother end-of-kernel tail.

#define F_DIM 256
#define P_DIM 3
#define NUM_SMS 148
#define BLOCKS_PER_SM 6
#define THREADS_PER_BLOCK 128
#define PD 6   // prefetch distance in grid-stride iterations

__device__ __forceinline__ float warp_reduce_sum(float v) {
    #pragma unroll
    for (int off = 16; off > 0; off >>= 1)
        v += __shfl_xor_sync(0xFFFFFFFFu, v, off);
    return v;
}

__device__ __forceinline__ float dot8(float4 a, float4 b, float4 wa, float4 wb) {
    float s = a.x * wa.x;
    s = fmaf(a.y, wa.y, s);
    s = fmaf(a.z, wa.z, s);
    s = fmaf(a.w, wa.w, s);
    s = fmaf(b.x, wb.x, s);
    s = fmaf(b.y, wb.y, s);
    s = fmaf(b.z, wb.z, s);
    s = fmaf(b.w, wb.w, s);
    return s;
}

// Softmax over 3 + weighted combine + streaming store for one window.
__device__ __forceinline__ void finish_window(
    float s0, float s1, float s2,
    float4 r0a, float4 r0b, float4 r1a, float4 r1b, float4 r2a, float4 r2b,
    float4* o)
{
    float m = fmaxf(s0, fmaxf(s1, s2));
    float e0 = __expf(s0 - m);
    float e1 = __expf(s1 - m);
    float e2 = __expf(s2 - m);
    float inv = 1.0f / (e0 + e1 + e2);
    float a0 = e0 * inv, a1 = e1 * inv, a2 = e2 * inv;

    float4 oa, ob;
    oa.x = fmaf(r2a.x, a2, fmaf(r1a.x, a1, r0a.x * a0));
    oa.y = fmaf(r2a.y, a2, fmaf(r1a.y, a1, r0a.y * a0));
    oa.z = fmaf(r2a.z, a2, fmaf(r1a.z, a1, r0a.z * a0));
    oa.w = fmaf(r2a.w, a2, fmaf(r1a.w, a1, r0a.w * a0));
    ob.x = fmaf(r2b.x, a2, fmaf(r1b.x, a1, r0b.x * a0));
    ob.y = fmaf(r2b.y, a2, fmaf(r1b.y, a1, r0b.y * a0));
    ob.z = fmaf(r2b.z, a2, fmaf(r1b.z, a1, r0b.z * a0));
    ob.w = fmaf(r2b.w, a2, fmaf(r1b.w, a1, r0b.w * a0));

    __stcs(o,     oa);
    __stcs(o + 1, ob);
}

__global__ void __launch_bounds__(THREADS_PER_BLOCK, BLOCKS_PER_SM)
gap_kernel(const float* __restrict__ x,
           const float* __restrict__ Ww,
           const float* __restrict__ Wb,
           float* __restrict__ out,
           int n_windows) {
    const int warp_id = (blockIdx.x * blockDim.x + threadIdx.x) >> 5;
    const int lane    = threadIdx.x & 31;
    const int n_warps = (int)((gridDim.x * blockDim.x) >> 5);

    if (warp_id >= n_windows) return;

    const int fv = lane * 2;  // float4 index within a row (row = 64 float4)

    const float4* Wv = reinterpret_cast<const float4*>(Ww);
    const float4 wa = Wv[fv], wb = Wv[fv + 1];
    const float bias = Wb[0];

    const float4* xbase = reinterpret_cast<const float4*>(x);
    float4*       obase = reinterpret_cast<float4*>(out);

    // Prologue: L2-prefetch the first PD windows of this warp's stream.
    // Window = 3072 B = 24 lines; lanes 0..23 take one 128B line each.
    if (lane < 24) {
        #pragma unroll
        for (int d = 0; d < PD; d++) {
            long long wi = warp_id + (long long)d * n_warps;
            if (wi < n_windows) {
                const char* p = (const char*)x + wi * 3072 + lane * 128;
                asm volatile("prefetch.global.L2 [%0];" :: "l"(p));
            }
        }
    }

    // Register prefetch of window 0 (window stride = 192 float4).
    int w = warp_id;
    const float4* xin0 = xbase + (long long)w * 192 + fv;
    float4 n0a = __ldcs(xin0 +   0), n0b = __ldcs(xin0 +   1);
    float4 n1a = __ldcs(xin0 +  64), n1b = __ldcs(xin0 +  65);
    float4 n2a = __ldcs(xin0 + 128), n2b = __ldcs(xin0 + 129);

    // Main loop: all iterations that have a successor window.
    for (; w + n_warps < n_windows; w += n_warps) {
        // L2-prefetch the window PD iterations ahead (registerless).
        {
            long long wp = w + (long long)PD * n_warps;
            if (wp < n_windows && lane < 24) {
                const char* p = (const char*)x + wp * 3072 + lane * 128;
                asm volatile("prefetch.global.L2 [%0];" :: "l"(p));
            }
        }

        // Current window = last register prefetch.
        float4 r0a = n0a, r0b = n0b;
        float4 r1a = n1a, r1b = n1b;
        float4 r2a = n2a, r2b = n2b;

        // Register prefetch of the next window BEFORE the compute chain.
        {
            const float4* nx = xbase + (long long)(w + n_warps) * 192 + fv;
            n0a = __ldcs(nx +   0); n0b = __ldcs(nx +   1);
            n1a = __ldcs(nx +  64); n1b = __ldcs(nx +  65);
            n2a = __ldcs(nx + 128); n2b = __ldcs(nx + 129);
        }

        float s0 = warp_reduce_sum(dot8(r0a, r0b, wa, wb)) + bias;
        float s1 = warp_reduce_sum(dot8(r1a, r1b, wa, wb)) + bias;
        float s2 = warp_reduce_sum(dot8(r2a, r2b, wa, wb)) + bias;

        finish_window(s0, s1, s2, r0a, r0b, r1a, r1b, r2a, r2b,
                      obase + (long long)w * 64 + fv);
    }

    // Peeled final iteration: consume the last prefetched window, no reload.
    {
        float s0 = warp_reduce_sum(dot8(n0a, n0b, wa, wb)) + bias;
        float s1 = warp_reduce_sum(dot8(n1a, n1b, wa, wb)) + bias;
        float s2 = warp_reduce_sum(dot8(n2a, n2b, wa, wb)) + bias;

        finish_window(s0, s1, s2, n0a, n0b, n1a, n1b, n2a, n2b,
                      obase + (long long)w * 64 + fv);
    }
}

extern "C" void kernel_launch(void* const* d_in, const int* in_sizes, int n_in,
                              void* d_out, int out_size) {
    const float* x  = (const float*)d_in[0];  // [32, 3072, 256]
    const float* Ww = (const float*)d_in[1];  // [256]
    const float* Wb = (const float*)d_in[2];  // [1]
    float* out = (float*)d_out;               // [32, 1024, 256, 1]

    const int n_windows = in_sizes[0] / (P_DIM * F_DIM);  // 32768
    const int blocks = NUM_SMS * BLOCKS_PER_SM;           // 888, exact-fit one wave

    gap_kernel<<<blocks, THREADS_PER_BLOCK>>>(x, Ww, Wb, out, n_windows);
}